// round 16
// baseline (speedup 1.0000x reference)
#include <cuda_runtime.h>
#include <math.h>

// LSTM decoder B=256,H=1024,I=1,O=512,T=512. Persistent kernel, 1 graph node.
// Weights SM-resident in smem; 512 threads (4 warps/SMSP) for latency hiding.

#define HID    1024
#define OUTF   512
#define TSTEPS 512
#define NBLK   128
#define NTHR   512
#define WP     1028           // weight row pitch (floats)
#define HPW    36             // h staging row pitch (floats), CHUNK + 4 pad
#define CHUNK  32
#define NCH    (HID / CHUNK)
#define HBUF   (256 * HPW)    // 9216 floats per h buffer

__device__ __align__(16) float g_h[2][256 * HID];
__device__ unsigned long long g_best[2][256];
__device__ int g_count;
__device__ unsigned g_sense;

#define F_WS   0
#define F_WLS  (32 * WP)             // 32896
#define F_H    (F_WLS + 4 * WP)      // 37008
#define F_XIN  (F_H + 2 * HBUF)      // 55440
#define F_BW   (F_XIN + 256)         // 55696
#define SMEM_FLOATS (F_BW + 64)      // 55760 floats = 223040 B

__device__ __forceinline__ void gridbar(unsigned sv) {
    __threadfence();
    __syncthreads();
    if (threadIdx.x == 0) {
        if (atomicAdd(&g_count, 1) == NBLK - 1) {
            atomicExch(&g_count, 0);
            __threadfence();
            atomicExch(&g_sense, sv ^ 1);
        } else {
            while (*(volatile unsigned*)&g_sense == sv) __nanosleep(32);
        }
    }
    __syncthreads();
}

__device__ __forceinline__ float sigf(float x) { return 1.f / (1.f + expf(-x)); }

__device__ __forceinline__ unsigned long long fma2(unsigned long long a,
                                                   unsigned long long b,
                                                   unsigned long long c) {
    unsigned long long d;
    asm("fma.rn.f32x2 %0, %1, %2, %3;" : "=l"(d) : "l"(a), "l"(b), "l"(c));
    return d;
}
__device__ __forceinline__ float lo32(unsigned long long a) { return __uint_as_float((unsigned)a); }
__device__ __forceinline__ float hi32(unsigned long long a) { return __uint_as_float((unsigned)(a >> 32)); }

__global__ __launch_bounds__(NTHR, 1)
void lstm_persistent(const float* __restrict__ z,
                     const float* __restrict__ w_ih,
                     const float* __restrict__ w_hh,
                     const float* __restrict__ b_ih,
                     const float* __restrict__ b_hh,
                     const float* __restrict__ w_lin,
                     const float* __restrict__ b_lin,
                     float* __restrict__ out)
{
    extern __shared__ float sm[];
    float* w_s   = sm + F_WS;
    float* wl_s  = sm + F_WLS;
    float* h_s   = sm + F_H;          // [buf][256 b][HPW]
    float* xin_s = sm + F_XIN;
    float* bw_s  = sm + F_BW;         // [0..31] bias, [32..63] w_ih

    const int blk = blockIdx.x;
    const int t   = threadIdx.x;
    const int rg  = t & 3;            // phase A row group 0..3
    const int bg  = t >> 2;           // phase A batch group 0..127 (b = bg, bg+128)
    const int srow = t & 255;         // staging: row
    const int skp  = t >> 8;          // staging: k-part (0/1, 16 floats each)
    const int bB  = t & 255;          // phase B batch row
    const int oh  = t >> 8;           // phase B o-pair (0/1)

    // ---- load resident weights once ----
    // slot rp -> (g = (rp>>2)&3, jl = 2*(rp&3) + (rp>>4));  j = blk*8 + jl
    if (t < 256) {
        for (int rp = 0; rp < 32; rp++) {
            int g  = (rp >> 2) & 3;
            int jl = 2 * (rp & 3) + (rp >> 4);
            const float* src = w_hh + (size_t)((g << 10) + (blk << 3) + jl) * HID;
            *(float4*)(w_s + rp * WP + t * 4) = *(const float4*)(src + t * 4);
        }
#pragma unroll
        for (int oo = 0; oo < 4; oo++) {
            const float* src = w_lin + (size_t)((blk << 2) + oo) * HID;
            *(float4*)(wl_s + oo * WP + t * 4) = *(const float4*)(src + t * 4);
        }
    }
    if (t < 32) {
        int g  = (t >> 2) & 3;
        int jl = 2 * (t & 3) + (t >> 4);
        int row = (g << 10) + (blk << 3) + jl;
        bw_s[t]      = b_ih[row] + b_hh[row];
        bw_s[32 + t] = w_ih[row];
    }
    float blB[2];
    blB[0] = b_lin[(blk << 2) + (oh << 1)];
    blB[1] = b_lin[(blk << 2) + (oh << 1) + 1];
    __syncthreads();

    float c_reg[2][2];                // [jlh][sl]
#pragma unroll
    for (int j = 0; j < 2; j++)
#pragma unroll
        for (int sl = 0; sl < 2; sl++) c_reg[j][sl] = 0.f;

    unsigned sense = *(volatile unsigned*)&g_sense;

    for (int s = 0; s < TSTEPS; s++) {
        const float* __restrict__ hin = (s == 0) ? z : g_h[(s + 1) & 1];
        float* __restrict__ hout = g_h[s & 1];

        // xin (decode last step's argmax) + reset this step's argmax buffer
        if (t < 256) {
            float x = 0.f;
            if (s > 0) {
                unsigned long long k = __ldcg(&g_best[(s + 1) & 1][t]);
                x = (float)(0xFFFFFFFFu - (unsigned)(k & 0xFFFFFFFFull));
            }
            xin_s[t] = x;
        }
        if (t < 2) g_best[s & 1][(blk << 1) + t] = 0ull;

        // ============ Phase A: gates GEMM (w smem-resident) ============
        unsigned long long acc[8][2];
#pragma unroll
        for (int i = 0; i < 8; i++) { acc[i][0] = 0ull; acc[i][1] = 0ull; }

        {   // prologue: stage chunk 0
            const float* p = hin + (size_t)srow * HID + skp * 16;
            float4 a0 = __ldcg((const float4*)(p + 0));
            float4 a1 = __ldcg((const float4*)(p + 4));
            float4 a2 = __ldcg((const float4*)(p + 8));
            float4 a3 = __ldcg((const float4*)(p + 12));
            float* d = h_s + srow * HPW + skp * 16;
            *(float4*)(d + 0) = a0; *(float4*)(d + 4)  = a1;
            *(float4*)(d + 8) = a2; *(float4*)(d + 12) = a3;
            __syncthreads();
        }
        int buf = 0;
        for (int c = 0; c < NCH; c++) {
            float4 a0, a1, a2, a3;
            const bool pre = (c + 1 < NCH);
            if (pre) {
                const float* p = hin + (size_t)srow * HID + (c + 1) * CHUNK + skp * 16;
                a0 = __ldcg((const float4*)(p + 0));
                a1 = __ldcg((const float4*)(p + 4));
                a2 = __ldcg((const float4*)(p + 8));
                a3 = __ldcg((const float4*)(p + 12));
            }
            const float* hb = h_s + buf * HBUF;
#pragma unroll
            for (int q = 0; q < 8; q++) {
                const int kw = c * CHUNK + q * 4;
                ulonglong2 wv[8];
#pragma unroll
                for (int i = 0; i < 8; i++)
                    wv[i] = *(const ulonglong2*)(w_s + (4 * i + rg) * WP + kw);
                ulonglong2 h0 = *(const ulonglong2*)(hb + bg * HPW + q * 4);
                ulonglong2 h1 = *(const ulonglong2*)(hb + (bg + 128) * HPW + q * 4);
#pragma unroll
                for (int i = 0; i < 8; i++) {
                    acc[i][0] = fma2(wv[i].x, h0.x, acc[i][0]);
                    acc[i][0] = fma2(wv[i].y, h0.y, acc[i][0]);
                    acc[i][1] = fma2(wv[i].x, h1.x, acc[i][1]);
                    acc[i][1] = fma2(wv[i].y, h1.y, acc[i][1]);
                }
            }
            if (pre) {
                float* d = h_s + (buf ^ 1) * HBUF + srow * HPW + skp * 16;
                *(float4*)(d + 0) = a0; *(float4*)(d + 4)  = a1;
                *(float4*)(d + 8) = a2; *(float4*)(d + 12) = a3;
            }
            __syncthreads();
            buf ^= 1;
        }

        // cell update: acc[i][sl], i = 4*jlh + g; rp = 4*i+rg; b = bg + 128*sl
#pragma unroll
        for (int sl = 0; sl < 2; sl++) {
            const int b = bg + (sl << 7);
            const float xv = xin_s[b];
            float hn2[2];
#pragma unroll
            for (int jlh = 0; jlh < 2; jlh++) {
                float pre4[4];
#pragma unroll
                for (int g = 0; g < 4; g++) {
                    const int i  = 4 * jlh + g;
                    const int rp = 4 * i + rg;
                    unsigned long long a = acc[i][sl];
                    pre4[g] = lo32(a) + hi32(a) + bw_s[rp] + xv * bw_s[32 + rp];
                }
                float cn = sigf(pre4[1]) * c_reg[jlh][sl] + sigf(pre4[0]) * tanhf(pre4[2]);
                c_reg[jlh][sl] = cn;
                hn2[jlh] = sigf(pre4[3]) * tanhf(cn);
            }
            *(float2*)(hout + (size_t)b * HID + (blk << 3) + 2 * rg) =
                make_float2(hn2[0], hn2[1]);
        }

        gridbar(sense); sense ^= 1;   // h_new + g_best resets visible

        // ============ Phase B: head GEMM + logits + argmax ============
        unsigned long long accB[2] = {0ull, 0ull};
        {   // prologue: stage chunk 0 of hout
            const float* p = hout + (size_t)srow * HID + skp * 16;
            float4 a0 = __ldcg((const float4*)(p + 0));
            float4 a1 = __ldcg((const float4*)(p + 4));
            float4 a2 = __ldcg((const float4*)(p + 8));
            float4 a3 = __ldcg((const float4*)(p + 12));
            float* d = h_s + srow * HPW + skp * 16;
            *(float4*)(d + 0) = a0; *(float4*)(d + 4)  = a1;
            *(float4*)(d + 8) = a2; *(float4*)(d + 12) = a3;
            __syncthreads();
        }
        buf = 0;
        for (int c = 0; c < NCH; c++) {
            float4 a0, a1, a2, a3;
            const bool pre = (c + 1 < NCH);
            if (pre) {
                const float* p = hout + (size_t)srow * HID + (c + 1) * CHUNK + skp * 16;
                a0 = __ldcg((const float4*)(p + 0));
                a1 = __ldcg((const float4*)(p + 4));
                a2 = __ldcg((const float4*)(p + 8));
                a3 = __ldcg((const float4*)(p + 12));
            }
            const float* hb = h_s + buf * HBUF + bB * HPW;
#pragma unroll
            for (int q = 0; q < 8; q++) {
                const int kw = c * CHUNK + q * 4;
                ulonglong2 hv = *(const ulonglong2*)(hb + q * 4);
                ulonglong2 w0 = *(const ulonglong2*)(wl_s + ((oh << 1) + 0) * WP + kw);
                ulonglong2 w1 = *(const ulonglong2*)(wl_s + ((oh << 1) + 1) * WP + kw);
                accB[0] = fma2(w0.x, hv.x, accB[0]);
                accB[0] = fma2(w0.y, hv.y, accB[0]);
                accB[1] = fma2(w1.x, hv.x, accB[1]);
                accB[1] = fma2(w1.y, hv.y, accB[1]);
            }
            if (pre) {
                float* d = h_s + (buf ^ 1) * HBUF + srow * HPW + skp * 16;
                *(float4*)(d + 0) = a0; *(float4*)(d + 4)  = a1;
                *(float4*)(d + 8) = a2; *(float4*)(d + 12) = a3;
            }
            __syncthreads();
            buf ^= 1;
        }

        {   // logits out + argmax partial
            float v0 = lo32(accB[0]) + hi32(accB[0]) + blB[0];
            float v1 = lo32(accB[1]) + hi32(accB[1]) + blB[1];
            *(float2*)(out + (size_t)bB * (TSTEPS * OUTF) + (size_t)s * OUTF
                       + (blk << 2) + (oh << 1)) = make_float2(v0, v1);
            unsigned o0 = (unsigned)((blk << 2) + (oh << 1));
            unsigned u0 = __float_as_uint(v0);
            u0 = (u0 & 0x80000000u) ? ~u0 : (u0 | 0x80000000u);
            unsigned u1 = __float_as_uint(v1);
            u1 = (u1 & 0x80000000u) ? ~u1 : (u1 | 0x80000000u);
            unsigned long long k0 = ((unsigned long long)u0 << 32)
                                  | (unsigned long long)(0xFFFFFFFFu - o0);
            unsigned long long k1 = ((unsigned long long)u1 << 32)
                                  | (unsigned long long)(0xFFFFFFFFu - (o0 + 1u));
            unsigned long long best = (k1 > k0) ? k1 : k0;
            atomicMax(&g_best[s & 1][bB], best);
        }

        gridbar(sense); sense ^= 1;   // argmax visible
    }
}

extern "C" void kernel_launch(void* const* d_in, const int* in_sizes, int n_in,
                              void* d_out, int out_size)
{
    (void)in_sizes; (void)n_in; (void)out_size;
    const float* z     = (const float*)d_in[0];
    const float* w_ih  = (const float*)d_in[1];
    const float* w_hh  = (const float*)d_in[2];
    const float* b_ih  = (const float*)d_in[3];
    const float* b_hh  = (const float*)d_in[4];
    const float* w_lin = (const float*)d_in[5];
    const float* b_lin = (const float*)d_in[6];
    float* out = (float*)d_out;

    static_assert(SMEM_FLOATS * 4 <= 227 * 1024, "smem budget");
    cudaFuncSetAttribute(lstm_persistent,
                         cudaFuncAttributeMaxDynamicSharedMemorySize,
                         SMEM_FLOATS * 4);
    lstm_persistent<<<NBLK, NTHR, SMEM_FLOATS * 4>>>(
        z, w_ih, w_hh, b_ih, b_hh, w_lin, b_lin, out);
}